// round 3
// baseline (speedup 1.0000x reference)
#include <cuda_runtime.h>

#define NN  192
#define NN2 (NN*NN)
#define NN3 (NN*NN*NN)

#define INV2DX     96.0f          // 1/(2*dx), dx = 1/N
#define MU_REF_F   1.8e-5f
#define CP_OVER_PR 1395.833333f   // 1005 / 0.72

#define TX 32
#define TY 8
#define CHUNK 48
#define PX (TX + 2)               // 34
#define PY (TY + 2)               // 10
#define NPTS (PX * PY)            // 340
#define NTHREADS (TX * TY)        // 256

__device__ __forceinline__ int wrapp(int i) { return (i == NN - 1) ? 0 : i + 1; }
__device__ __forceinline__ int wrapm(int i) { return (i == 0) ? NN - 1 : i - 1; }
__device__ __forceinline__ int wrapg(int i) { return (i < 0) ? i + NN : ((i >= NN) ? i - NN : i); }

// Compute the 9 flux fields (tau00,tau01,tau02,tau11,tau12,tau22, E0,E1,E2)
// at wrapped global point (gz, gy, gx).
__device__ __forceinline__ void compute_flux(const float* __restrict__ u,
                                             const float* __restrict__ T,
                                             int gz, int gy, int gx,
                                             float f[9])
{
    const int zp = wrapp(gz), zm = wrapm(gz);
    const int yp = wrapp(gy), ym = wrapm(gy);
    const int xp = wrapp(gx), xm = wrapm(gx);

    const int i_c  = gz * NN2 + gy * NN + gx;
    const int i_zp = zp * NN2 + gy * NN + gx;
    const int i_zm = zm * NN2 + gy * NN + gx;
    const int i_yp = gz * NN2 + yp * NN + gx;
    const int i_ym = gz * NN2 + ym * NN + gx;
    const int i_xp = gz * NN2 + gy * NN + xp;
    const int i_xm = gz * NN2 + gy * NN + xm;

    float g[3][3], uc[3];
#pragma unroll
    for (int i = 0; i < 3; i++) {
        const float* ui = u + i * NN3;
        uc[i]   = __ldg(ui + i_c);
        g[i][0] = (__ldg(ui + i_zp) - __ldg(ui + i_zm)) * INV2DX;
        g[i][1] = (__ldg(ui + i_yp) - __ldg(ui + i_ym)) * INV2DX;
        g[i][2] = (__ldg(ui + i_xp) - __ldg(ui + i_xm)) * INV2DX;
    }

    const float divu = g[0][0] + g[1][1] + g[2][2];
    const float Tc   = __ldg(T + i_c);
    const float mu   = MU_REF_F * __powf(Tc, 0.7f);  // T nondimensional
    const float kk   = mu * CP_OVER_PR;
    const float lam  = -(2.0f / 3.0f) * mu * divu;

    const float t00 = 2.0f * mu * g[0][0] + lam;
    const float t11 = 2.0f * mu * g[1][1] + lam;
    const float t22 = 2.0f * mu * g[2][2] + lam;
    const float t01 = mu * (g[0][1] + g[1][0]);
    const float t02 = mu * (g[0][2] + g[2][0]);
    const float t12 = mu * (g[1][2] + g[2][1]);

    const float gT0 = (__ldg(T + i_zp) - __ldg(T + i_zm)) * INV2DX;
    const float gT1 = (__ldg(T + i_yp) - __ldg(T + i_ym)) * INV2DX;
    const float gT2 = (__ldg(T + i_xp) - __ldg(T + i_xm)) * INV2DX;

    f[0] = t00; f[1] = t01; f[2] = t02;
    f[3] = t11; f[4] = t12; f[5] = t22;
    f[6] = kk * gT0 + uc[0] * t00 + uc[1] * t01 + uc[2] * t02;
    f[7] = kk * gT1 + uc[0] * t01 + uc[1] * t11 + uc[2] * t12;
    f[8] = kk * gT2 + uc[0] * t02 + uc[1] * t12 + uc[2] * t22;
}

__global__ void __launch_bounds__(NTHREADS) fused_diffusion(const float* __restrict__ u,
                                                            const float* __restrict__ T,
                                                            float* __restrict__ out)
{
    __shared__ float sF[3][9][PY][PX];   // 3 rotating flux planes, 36.7 KB

    const int tid = threadIdx.y * TX + threadIdx.x;
    const int x0 = blockIdx.x * TX;
    const int y0 = blockIdx.y * TY;
    const int z0 = blockIdx.z * CHUNK;

    // Loop-invariant decomposition of the two fill points per thread.
    const int p0 = tid;                  // < 340 always
    const int p1 = tid + NTHREADS;       // valid if < NPTS
    const int f0y = p0 / PX, f0x = p0 - f0y * PX;
    const int f1y = p1 / PX, f1x = p1 - f1y * PX;
    const int g0y = wrapg(y0 + f0y - 1), g0x = wrapg(x0 + f0x - 1);
    const int g1y = wrapg(y0 + f1y - 1), g1x = wrapg(x0 + f1x - 1);
    const bool has1 = (p1 < NPTS);

    // Prologue: planes z0-1 and z0
    {
        float f[9];
        compute_flux(u, T, wrapg(z0 - 1), g0y, g0x, f);
#pragma unroll
        for (int c = 0; c < 9; c++) sF[0][c][f0y][f0x] = f[c];
        if (has1) {
            compute_flux(u, T, wrapg(z0 - 1), g1y, g1x, f);
#pragma unroll
            for (int c = 0; c < 9; c++) sF[0][c][f1y][f1x] = f[c];
        }
        compute_flux(u, T, z0, g0y, g0x, f);
#pragma unroll
        for (int c = 0; c < 9; c++) sF[1][c][f0y][f0x] = f[c];
        if (has1) {
            compute_flux(u, T, z0, g1y, g1x, f);
#pragma unroll
            for (int c = 0; c < 9; c++) sF[1][c][f1y][f1x] = f[c];
        }
    }

    const int tx = threadIdx.x, ty = threadIdx.y;
    const int gx = x0 + tx, gy = y0 + ty;
    const int fx = tx + 1, fy = ty + 1;

    for (int zi = 0; zi < CHUNK; zi++) {
        const int z  = z0 + zi;
        const int bA = zi % 3;          // plane z-1
        const int bB = (zi + 1) % 3;    // plane z
        const int bC = (zi + 2) % 3;    // plane z+1 (being filled)

        __syncthreads();   // previous iteration's reads of sF[bC] are done
        {
            const int znext = wrapp(z);   // z+1 wrapped (z in [0,191])
            float f[9];
            compute_flux(u, T, znext, g0y, g0x, f);
#pragma unroll
            for (int c = 0; c < 9; c++) sF[bC][c][f0y][f0x] = f[c];
            if (has1) {
                compute_flux(u, T, znext, g1y, g1x, f);
#pragma unroll
                for (int c = 0; c < 9; c++) sF[bC][c][f1y][f1x] = f[c];
            }
        }
        __syncthreads();

        float (*A)[PY][PX] = sF[bA];
        float (*B)[PY][PX] = sF[bB];
        float (*C)[PY][PX] = sF[bC];

        const float mom0 = (C[0][fy][fx] - A[0][fy][fx])
                         + (B[1][fy + 1][fx] - B[1][fy - 1][fx])
                         + (B[2][fy][fx + 1] - B[2][fy][fx - 1]);
        const float mom1 = (C[1][fy][fx] - A[1][fy][fx])
                         + (B[3][fy + 1][fx] - B[3][fy - 1][fx])
                         + (B[4][fy][fx + 1] - B[4][fy][fx - 1]);
        const float mom2 = (C[2][fy][fx] - A[2][fy][fx])
                         + (B[4][fy + 1][fx] - B[4][fy - 1][fx])
                         + (B[5][fy][fx + 1] - B[5][fy][fx - 1]);
        const float en   = (C[6][fy][fx] - A[6][fy][fx])
                         + (B[7][fy + 1][fx] - B[7][fy - 1][fx])
                         + (B[8][fy][fx + 1] - B[8][fy][fx - 1]);

        const int idx = z * NN2 + gy * NN + gx;
        out[0 * NN3 + idx] = 0.0f;
        out[1 * NN3 + idx] = mom0 * INV2DX;
        out[2 * NN3 + idx] = mom1 * INV2DX;
        out[3 * NN3 + idx] = mom2 * INV2DX;
        out[4 * NN3 + idx] = en * INV2DX;
    }
}

extern "C" void kernel_launch(void* const* d_in, const int* in_sizes, int n_in,
                              void* d_out, int out_size)
{
    const float* u = (const float*)d_in[0];   // [3, N, N, N]
    const float* T = (const float*)d_in[1];   // [N, N, N]
    float* out = (float*)d_out;               // [5, N, N, N]

    dim3 grid(NN / TX, NN / TY, NN / CHUNK);  // 6 x 24 x 4
    dim3 block(TX, TY, 1);
    fused_diffusion<<<grid, block>>>(u, T, out);
}

// round 4
// speedup vs baseline: 1.6295x; 1.6295x over previous
#include <cuda_runtime.h>

#define NN  192
#define NN2 (NN*NN)
#define NN3 (NN*NN*NN)

#define INV2DX     96.0f          // 1/(2*dx), dx = 1/N
#define MU_REF_F   1.8e-5f
#define CP_OVER_PR 1395.833333f   // 1005 / 0.72

#define TX 32
#define TY 8
#define CHUNK 48
#define PX  (TX + 2)              // 34  flux plane (halo 1)
#define PY  (TY + 2)              // 10
#define PX2 (TX + 4)              // 36  u/T plane (halo 2)
#define PY2 (TY + 4)              // 12
#define NPTS (PX * PY)            // 340 flux points
#define NSTG (PX2 * PY2)          // 432 staging points
#define NTHREADS (TX * TY)        // 256

#define SU_PLANE  (4 * PY2 * PX2) // 1728 floats per u/T plane slot
#define SFH_PLANE (7 * PY * PX)   // 2380 floats: t01,t02,t11,t12,t22,E1,E2 (with halo)
#define SFC_PLANE (2 * TY * TX)   // 512  floats: t00,E0 (center only)
#define SMEM_FLOATS (3 * SU_PLANE + 3 * SFH_PLANE + 3 * SFC_PLANE)  // 13860
#define SMEM_BYTES  (SMEM_FLOATS * 4)                                // 55440

__device__ __forceinline__ int wrapg(int i) { return (i < 0) ? i + NN : ((i >= NN) ? i - NN : i); }
__device__ __forceinline__ int slot3(int p) { return ((p % 3) + 3) % 3; }

// ---- stage one u/T plane (global -> smem), direct ----
__device__ __forceinline__ void stage_direct(const float* __restrict__ u,
                                             const float* __restrict__ T,
                                             float* sU, int slot, int p,
                                             int sgb0, int suo0,
                                             int sgb1, int suo1, bool hasq1)
{
    const int zo = wrapg(p) * NN2;
    float* b = sU + slot * SU_PLANE;
    b[0 * PY2 * PX2 + suo0] = __ldg(u + 0 * NN3 + zo + sgb0);
    b[1 * PY2 * PX2 + suo0] = __ldg(u + 1 * NN3 + zo + sgb0);
    b[2 * PY2 * PX2 + suo0] = __ldg(u + 2 * NN3 + zo + sgb0);
    b[3 * PY2 * PX2 + suo0] = __ldg(T + zo + sgb0);
    if (hasq1) {
        b[0 * PY2 * PX2 + suo1] = __ldg(u + 0 * NN3 + zo + sgb1);
        b[1 * PY2 * PX2 + suo1] = __ldg(u + 1 * NN3 + zo + sgb1);
        b[2 * PY2 * PX2 + suo1] = __ldg(u + 2 * NN3 + zo + sgb1);
        b[3 * PY2 * PX2 + suo1] = __ldg(T + zo + sgb1);
    }
}

// ---- prefetch one u/T plane (global -> registers) ----
__device__ __forceinline__ void prefetch_plane(const float* __restrict__ u,
                                               const float* __restrict__ T,
                                               int p, int sgb0, int sgb1, bool hasq1,
                                               float pr0[4], float pr1[4])
{
    const int zo = wrapg(p) * NN2;
    pr0[0] = __ldg(u + 0 * NN3 + zo + sgb0);
    pr0[1] = __ldg(u + 1 * NN3 + zo + sgb0);
    pr0[2] = __ldg(u + 2 * NN3 + zo + sgb0);
    pr0[3] = __ldg(T + zo + sgb0);
    if (hasq1) {
        pr1[0] = __ldg(u + 0 * NN3 + zo + sgb1);
        pr1[1] = __ldg(u + 1 * NN3 + zo + sgb1);
        pr1[2] = __ldg(u + 2 * NN3 + zo + sgb1);
        pr1[3] = __ldg(T + zo + sgb1);
    }
}

// ---- store prefetched registers into a smem plane slot ----
__device__ __forceinline__ void sts_prefetch(float* sU, int slot,
                                             int suo0, int suo1, bool hasq1,
                                             const float pr0[4], const float pr1[4])
{
    float* b = sU + slot * SU_PLANE;
    b[0 * PY2 * PX2 + suo0] = pr0[0];
    b[1 * PY2 * PX2 + suo0] = pr0[1];
    b[2 * PY2 * PX2 + suo0] = pr0[2];
    b[3 * PY2 * PX2 + suo0] = pr0[3];
    if (hasq1) {
        b[0 * PY2 * PX2 + suo1] = pr1[0];
        b[1 * PY2 * PX2 + suo1] = pr1[1];
        b[2 * PY2 * PX2 + suo1] = pr1[2];
        b[3 * PY2 * PX2 + suo1] = pr1[3];
    }
}

// ---- compute flux at one point from smem planes, store to smem flux ----
__device__ __forceinline__ void fill_point(const float* sU, float* sFh, float* sFc,
                                           int sm_, int sc_, int sp_, int fslot,
                                           int uoff, int fy, int fx)
{
    const float* Pm = sU + sm_ * SU_PLANE;
    const float* Pc = sU + sc_ * SU_PLANE;
    const float* Pp = sU + sp_ * SU_PLANE;

    float g[3][3], uc[3];
#pragma unroll
    for (int i = 0; i < 3; i++) {
        const float* Cm = Pm + i * PY2 * PX2;
        const float* Cc = Pc + i * PY2 * PX2;
        const float* Cp = Pp + i * PY2 * PX2;
        uc[i]   = Cc[uoff];
        g[i][0] = (Cp[uoff] - Cm[uoff]) * INV2DX;          // d/dz
        g[i][1] = (Cc[uoff + PX2] - Cc[uoff - PX2]) * INV2DX;  // d/dy
        g[i][2] = (Cc[uoff + 1] - Cc[uoff - 1]) * INV2DX;      // d/dx
    }
    const float* Tm = Pm + 3 * PY2 * PX2;
    const float* Tc_ = Pc + 3 * PY2 * PX2;
    const float* Tp = Pp + 3 * PY2 * PX2;

    const float Tv  = Tc_[uoff];
    const float gT0 = (Tp[uoff] - Tm[uoff]) * INV2DX;
    const float gT1 = (Tc_[uoff + PX2] - Tc_[uoff - PX2]) * INV2DX;
    const float gT2 = (Tc_[uoff + 1] - Tc_[uoff - 1]) * INV2DX;

    const float divu = g[0][0] + g[1][1] + g[2][2];
    const float mu   = MU_REF_F * __powf(Tv, 0.7f);
    const float kk   = mu * CP_OVER_PR;
    const float lam  = -(2.0f / 3.0f) * mu * divu;

    const float t00 = 2.0f * mu * g[0][0] + lam;
    const float t11 = 2.0f * mu * g[1][1] + lam;
    const float t22 = 2.0f * mu * g[2][2] + lam;
    const float t01 = mu * (g[0][1] + g[1][0]);
    const float t02 = mu * (g[0][2] + g[2][0]);
    const float t12 = mu * (g[1][2] + g[2][1]);

    const float E0 = kk * gT0 + uc[0] * t00 + uc[1] * t01 + uc[2] * t02;
    const float E1 = kk * gT1 + uc[0] * t01 + uc[1] * t11 + uc[2] * t12;
    const float E2 = kk * gT2 + uc[0] * t02 + uc[1] * t12 + uc[2] * t22;

    float* H = sFh + fslot * SFH_PLANE;
    const int ho = fy * PX + fx;
    H[0 * PY * PX + ho] = t01;
    H[1 * PY * PX + ho] = t02;
    H[2 * PY * PX + ho] = t11;
    H[3 * PY * PX + ho] = t12;
    H[4 * PY * PX + ho] = t22;
    H[5 * PY * PX + ho] = E1;
    H[6 * PY * PX + ho] = E2;
    if (fy >= 1 && fy < PY - 1 && fx >= 1 && fx < PX - 1) {
        float* Cq = sFc + fslot * SFC_PLANE;
        const int co = (fy - 1) * TX + (fx - 1);
        Cq[co]           = t00;
        Cq[TY * TX + co] = E0;
    }
}

__global__ void __launch_bounds__(NTHREADS, 4)
fused2(const float* __restrict__ u, const float* __restrict__ T, float* __restrict__ out)
{
    extern __shared__ float smem_pool[];
    float* sU  = smem_pool;                                // [3][4][PY2][PX2]
    float* sFh = smem_pool + 3 * SU_PLANE;                 // [3][7][PY][PX]
    float* sFc = smem_pool + 3 * SU_PLANE + 3 * SFH_PLANE; // [3][2][TY][TX]

    const int tid = threadIdx.y * TX + threadIdx.x;
    const int x0 = blockIdx.x * TX;
    const int y0 = blockIdx.y * TY;
    const int z0 = blockIdx.z * CHUNK;

    // ---- loop-invariant staging coords (2 points per thread) ----
    int sgb0, suo0, sgb1, suo1;
    bool hasq1;
    {
        const int q0 = tid;
        const int sy0 = q0 / PX2, sx0 = q0 - sy0 * PX2;
        sgb0 = wrapg(y0 + sy0 - 2) * NN + wrapg(x0 + sx0 - 2);
        suo0 = sy0 * PX2 + sx0;
        const int q1 = tid + NTHREADS;
        hasq1 = (q1 < NSTG);
        const int qq = hasq1 ? q1 : 0;
        const int sy1 = qq / PX2, sx1 = qq - sy1 * PX2;
        sgb1 = wrapg(y0 + sy1 - 2) * NN + wrapg(x0 + sx1 - 2);
        suo1 = sy1 * PX2 + sx1;
    }

    // ---- loop-invariant flux-fill coords (2 points per thread) ----
    int fy0, fx0, uoff0, fy1, fx1, uoff1;
    bool hasp1;
    {
        const int p0 = tid;
        fy0 = p0 / PX; fx0 = p0 - fy0 * PX;
        uoff0 = (fy0 + 1) * PX2 + (fx0 + 1);
        const int p1 = tid + NTHREADS;
        hasp1 = (p1 < NPTS);
        const int pp = hasp1 ? p1 : 0;
        fy1 = pp / PX; fx1 = pp - fy1 * PX;
        uoff1 = (fy1 + 1) * PX2 + (fx1 + 1);
    }

    float pr0[4], pr1[4];

    // ================= prologue =================
    stage_direct(u, T, sU, slot3(z0 - 2), z0 - 2, sgb0, suo0, sgb1, suo1, hasq1);
    stage_direct(u, T, sU, slot3(z0 - 1), z0 - 1, sgb0, suo0, sgb1, suo1, hasq1);
    stage_direct(u, T, sU, slot3(z0),     z0,     sgb0, suo0, sgb1, suo1, hasq1);
    __syncthreads();

    // prefetch plane z0+1 while filling flux z0-1
    prefetch_plane(u, T, z0 + 1, sgb0, sgb1, hasq1, pr0, pr1);
    fill_point(sU, sFh, sFc, slot3(z0 - 2), slot3(z0 - 1), slot3(z0), slot3(z0 - 1), uoff0, fy0, fx0);
    if (hasp1)
        fill_point(sU, sFh, sFc, slot3(z0 - 2), slot3(z0 - 1), slot3(z0), slot3(z0 - 1), uoff1, fy1, fx1);
    __syncthreads();

    sts_prefetch(sU, slot3(z0 + 1), suo0, suo1, hasq1, pr0, pr1);
    __syncthreads();

    // prefetch plane z0+2 while filling flux z0
    prefetch_plane(u, T, z0 + 2, sgb0, sgb1, hasq1, pr0, pr1);
    fill_point(sU, sFh, sFc, slot3(z0 - 1), slot3(z0), slot3(z0 + 1), slot3(z0), uoff0, fy0, fx0);
    if (hasp1)
        fill_point(sU, sFh, sFc, slot3(z0 - 1), slot3(z0), slot3(z0 + 1), slot3(z0), uoff1, fy1, fx1);
    __syncthreads();

    // ---- output coords ----
    const int tx = threadIdx.x, ty = threadIdx.y;
    const int gx = x0 + tx, gy = y0 + ty;
    const int ho = (ty + 1) * PX + (tx + 1);
    const int co = ty * TX + tx;

    // ================= main loop =================
    for (int zi = 0; zi < CHUNK; zi++) {
        const int z = z0 + zi;

        // 1. commit prefetched plane z+2 (overwrites slot of z-1, no longer read)
        sts_prefetch(sU, slot3(z + 2), suo0, suo1, hasq1, pr0, pr1);
        __syncthreads();

        // 2. prefetch plane z+3 for next iteration (latency hidden under fill+output)
        if (zi + 1 < CHUNK)
            prefetch_plane(u, T, z + 3, sgb0, sgb1, hasq1, pr0, pr1);

        // 3. fill flux plane z+1 from smem planes z, z+1, z+2
        fill_point(sU, sFh, sFc, slot3(z), slot3(z + 1), slot3(z + 2), slot3(z + 1), uoff0, fy0, fx0);
        if (hasp1)
            fill_point(sU, sFh, sFc, slot3(z), slot3(z + 1), slot3(z + 2), slot3(z + 1), uoff1, fy1, fx1);
        __syncthreads();

        // 4. output plane z from flux planes z-1, z, z+1
        const float* HA = sFh + slot3(z - 1) * SFH_PLANE;
        const float* HB = sFh + slot3(z)     * SFH_PLANE;
        const float* HC = sFh + slot3(z + 1) * SFH_PLANE;
        const float* CA = sFc + slot3(z - 1) * SFC_PLANE;
        const float* CC = sFc + slot3(z + 1) * SFC_PLANE;

        const float mom0 = (CC[co] - CA[co])                                      // t00 z
                         + (HB[0 * PY * PX + ho + PX] - HB[0 * PY * PX + ho - PX]) // t01 y
                         + (HB[1 * PY * PX + ho + 1]  - HB[1 * PY * PX + ho - 1]); // t02 x
        const float mom1 = (HC[0 * PY * PX + ho] - HA[0 * PY * PX + ho])          // t01 z
                         + (HB[2 * PY * PX + ho + PX] - HB[2 * PY * PX + ho - PX]) // t11 y
                         + (HB[3 * PY * PX + ho + 1]  - HB[3 * PY * PX + ho - 1]); // t12 x
        const float mom2 = (HC[1 * PY * PX + ho] - HA[1 * PY * PX + ho])          // t02 z
                         + (HB[3 * PY * PX + ho + PX] - HB[3 * PY * PX + ho - PX]) // t12 y
                         + (HB[4 * PY * PX + ho + 1]  - HB[4 * PY * PX + ho - 1]); // t22 x
        const float en   = (CC[TY * TX + co] - CA[TY * TX + co])                  // E0 z
                         + (HB[5 * PY * PX + ho + PX] - HB[5 * PY * PX + ho - PX]) // E1 y
                         + (HB[6 * PY * PX + ho + 1]  - HB[6 * PY * PX + ho - 1]); // E2 x

        const int idx = z * NN2 + gy * NN + gx;
        out[0 * NN3 + idx] = 0.0f;
        out[1 * NN3 + idx] = mom0 * INV2DX;
        out[2 * NN3 + idx] = mom1 * INV2DX;
        out[3 * NN3 + idx] = mom2 * INV2DX;
        out[4 * NN3 + idx] = en * INV2DX;
    }
}

extern "C" void kernel_launch(void* const* d_in, const int* in_sizes, int n_in,
                              void* d_out, int out_size)
{
    const float* u = (const float*)d_in[0];   // [3, N, N, N]
    const float* T = (const float*)d_in[1];   // [N, N, N]
    float* out = (float*)d_out;               // [5, N, N, N]

    cudaFuncSetAttribute(fused2, cudaFuncAttributeMaxDynamicSharedMemorySize, SMEM_BYTES);

    dim3 grid(NN / TX, NN / TY, NN / CHUNK);  // 6 x 24 x 4 = 576 blocks
    dim3 block(TX, TY, 1);
    fused2<<<grid, block, SMEM_BYTES>>>(u, T, out);
}

// round 5
// speedup vs baseline: 1.7725x; 1.0878x over previous
#include <cuda_runtime.h>

#define NN  192
#define NN2 (NN*NN)
#define NN3 (NN*NN*NN)

#define INV2DX     96.0f          // 1/(2*dx), dx = 1/N
#define MU_REF_F   1.8e-5f
#define CP_OVER_PR 1395.833333f   // 1005 / 0.72

#define TX 32
#define TY 8
#define CHUNK 48
#define PX  (TX + 2)              // 34  flux plane (halo 1)
#define PY  (TY + 2)              // 10
#define PX2 (TX + 4)              // 36  u/T plane (halo 2)
#define PY2 (TY + 4)              // 12
#define NPTS   (PX * PY)          // 340 flux points
#define NHALO  (NPTS - TX * TY)   // 84  halo-ring flux points
#define NSTG   (PX2 * PY2)        // 432 staging points
#define NTHREADS (TX * TY)        // 256

#define SU_PLANE  (4 * PY2 * PX2) // 1728 floats per u/T plane slot
#define SFH_PLANE (7 * PY * PX)   // 2380 floats: t01,t02,t11,t12,t22,E1,E2
#define SMEM_FLOATS (3 * SU_PLANE + 3 * SFH_PLANE)   // 12324
#define SMEM_BYTES  (SMEM_FLOATS * 4)                // 49296

__device__ __forceinline__ int wrapg(int i) { return (i < 0) ? i + NN : ((i >= NN) ? i - NN : i); }
__device__ __forceinline__ int slot3(int p) { return ((p % 3) + 3) % 3; }

// ---- stage one u/T plane (global -> smem), direct ----
__device__ __forceinline__ void stage_direct(const float* __restrict__ u,
                                             const float* __restrict__ T,
                                             float* sU, int slot, int p,
                                             int sgb0, int suo0,
                                             int sgb1, int suo1, bool hasq1)
{
    const int zo = wrapg(p) * NN2;
    float* b = sU + slot * SU_PLANE;
    b[0 * PY2 * PX2 + suo0] = __ldg(u + 0 * NN3 + zo + sgb0);
    b[1 * PY2 * PX2 + suo0] = __ldg(u + 1 * NN3 + zo + sgb0);
    b[2 * PY2 * PX2 + suo0] = __ldg(u + 2 * NN3 + zo + sgb0);
    b[3 * PY2 * PX2 + suo0] = __ldg(T + zo + sgb0);
    if (hasq1) {
        b[0 * PY2 * PX2 + suo1] = __ldg(u + 0 * NN3 + zo + sgb1);
        b[1 * PY2 * PX2 + suo1] = __ldg(u + 1 * NN3 + zo + sgb1);
        b[2 * PY2 * PX2 + suo1] = __ldg(u + 2 * NN3 + zo + sgb1);
        b[3 * PY2 * PX2 + suo1] = __ldg(T + zo + sgb1);
    }
}

// ---- prefetch one u/T plane (global -> registers) ----
__device__ __forceinline__ void prefetch_plane(const float* __restrict__ u,
                                               const float* __restrict__ T,
                                               int p, int sgb0, int sgb1, bool hasq1,
                                               float pr0[4], float pr1[4])
{
    const int zo = wrapg(p) * NN2;
    pr0[0] = __ldg(u + 0 * NN3 + zo + sgb0);
    pr0[1] = __ldg(u + 1 * NN3 + zo + sgb0);
    pr0[2] = __ldg(u + 2 * NN3 + zo + sgb0);
    pr0[3] = __ldg(T + zo + sgb0);
    if (hasq1) {
        pr1[0] = __ldg(u + 0 * NN3 + zo + sgb1);
        pr1[1] = __ldg(u + 1 * NN3 + zo + sgb1);
        pr1[2] = __ldg(u + 2 * NN3 + zo + sgb1);
        pr1[3] = __ldg(T + zo + sgb1);
    }
}

__device__ __forceinline__ void sts_prefetch(float* sU, int slot,
                                             int suo0, int suo1, bool hasq1,
                                             const float pr0[4], const float pr1[4])
{
    float* b = sU + slot * SU_PLANE;
    b[0 * PY2 * PX2 + suo0] = pr0[0];
    b[1 * PY2 * PX2 + suo0] = pr0[1];
    b[2 * PY2 * PX2 + suo0] = pr0[2];
    b[3 * PY2 * PX2 + suo0] = pr0[3];
    if (hasq1) {
        b[0 * PY2 * PX2 + suo1] = pr1[0];
        b[1 * PY2 * PX2 + suo1] = pr1[1];
        b[2 * PY2 * PX2 + suo1] = pr1[2];
        b[3 * PY2 * PX2 + suo1] = pr1[3];
    }
}

// ---- flux math from gradients: writes 7 halo comps to smem, returns t00,t01,t02,E0 ----
__device__ __forceinline__ void flux_finish(const float c4[4], const float gz4[4],
                                            const float gy4[4], const float gx4[4],
                                            float* H, int ho, float fz[4])
{
    const float divu = gz4[0] + gy4[1] + gx4[2];
    const float mu   = MU_REF_F * __powf(c4[3], 0.7f);
    const float kk   = mu * CP_OVER_PR;
    const float lam  = -(2.0f / 3.0f) * mu * divu;

    const float t00 = 2.0f * mu * gz4[0] + lam;
    const float t11 = 2.0f * mu * gy4[1] + lam;
    const float t22 = 2.0f * mu * gx4[2] + lam;
    const float t01 = mu * (gy4[0] + gz4[1]);
    const float t02 = mu * (gx4[0] + gz4[2]);
    const float t12 = mu * (gx4[1] + gy4[2]);

    const float E0 = kk * gz4[3] + c4[0] * t00 + c4[1] * t01 + c4[2] * t02;
    const float E1 = kk * gy4[3] + c4[0] * t01 + c4[1] * t11 + c4[2] * t12;
    const float E2 = kk * gx4[3] + c4[0] * t02 + c4[1] * t12 + c4[2] * t22;

    H[0 * PY * PX + ho] = t01;
    H[1 * PY * PX + ho] = t02;
    H[2 * PY * PX + ho] = t11;
    H[3 * PY * PX + ho] = t12;
    H[4 * PY * PX + ho] = t22;
    H[5 * PY * PX + ho] = E1;
    H[6 * PY * PX + ho] = E2;

    fz[0] = t00; fz[1] = t01; fz[2] = t02; fz[3] = E0;
}

// ---- center-point flux: full-warp, x-derivs via shuffles ----
__device__ __forceinline__ void flux_center(const float* sU, float* sFh,
                                            int sm_, int sc_, int sp_, int fslot,
                                            int uoff, int ho, int tx, float fz[4])
{
    const float* Pm = sU + sm_ * SU_PLANE;
    const float* Pc = sU + sc_ * SU_PLANE;
    const float* Pp = sU + sp_ * SU_PLANE;

    float c4[4], gz4[4], gy4[4], gx4[4];
#pragma unroll
    for (int i = 0; i < 4; i++) {
        const float* Cm = Pm + i * PY2 * PX2;
        const float* Cc = Pc + i * PY2 * PX2;
        const float* Cp = Pp + i * PY2 * PX2;
        const float c = Cc[uoff];
        float xl = __shfl_up_sync(0xffffffffu, c, 1);
        if (tx == 0)  xl = Cc[uoff - 1];
        float xr = __shfl_down_sync(0xffffffffu, c, 1);
        if (tx == 31) xr = Cc[uoff + 1];
        c4[i]  = c;
        gz4[i] = (Cp[uoff] - Cm[uoff]) * INV2DX;
        gy4[i] = (Cc[uoff + PX2] - Cc[uoff - PX2]) * INV2DX;
        gx4[i] = (xr - xl) * INV2DX;
    }
    flux_finish(c4, gz4, gy4, gx4, sFh + fslot * SFH_PLANE, ho, fz);
}

// ---- halo-ring flux: generic LDS version ----
__device__ __forceinline__ void flux_halo(const float* sU, float* sFh,
                                          int sm_, int sc_, int sp_, int fslot,
                                          int uoff, int ho)
{
    const float* Pm = sU + sm_ * SU_PLANE;
    const float* Pc = sU + sc_ * SU_PLANE;
    const float* Pp = sU + sp_ * SU_PLANE;

    float c4[4], gz4[4], gy4[4], gx4[4];
#pragma unroll
    for (int i = 0; i < 4; i++) {
        const float* Cm = Pm + i * PY2 * PX2;
        const float* Cc = Pc + i * PY2 * PX2;
        const float* Cp = Pp + i * PY2 * PX2;
        c4[i]  = Cc[uoff];
        gz4[i] = (Cp[uoff] - Cm[uoff]) * INV2DX;
        gy4[i] = (Cc[uoff + PX2] - Cc[uoff - PX2]) * INV2DX;
        gx4[i] = (Cc[uoff + 1] - Cc[uoff - 1]) * INV2DX;
    }
    float fz_dummy[4];
    flux_finish(c4, gz4, gy4, gx4, sFh + fslot * SFH_PLANE, ho, fz_dummy);
}

__global__ void __launch_bounds__(NTHREADS, 4)
fused3(const float* __restrict__ u, const float* __restrict__ T, float* __restrict__ out)
{
    extern __shared__ float smem_pool[];
    float* sU  = smem_pool;                 // [3][4][PY2][PX2]
    float* sFh = smem_pool + 3 * SU_PLANE;  // [3][7][PY][PX]

    const int tid = threadIdx.y * TX + threadIdx.x;
    const int tx = threadIdx.x, ty = threadIdx.y;
    const int x0 = blockIdx.x * TX;
    const int y0 = blockIdx.y * TY;
    const int z0 = blockIdx.z * CHUNK;

    // ---- staging coords (2 points per thread) ----
    int sgb0, suo0, sgb1, suo1;
    bool hasq1;
    {
        const int q0 = tid;
        const int sy0 = q0 / PX2, sx0 = q0 - sy0 * PX2;
        sgb0 = wrapg(y0 + sy0 - 2) * NN + wrapg(x0 + sx0 - 2);
        suo0 = sy0 * PX2 + sx0;
        const int q1 = tid + NTHREADS;
        hasq1 = (q1 < NSTG);
        const int qq = hasq1 ? q1 : 0;
        const int sy1 = qq / PX2, sx1 = qq - sy1 * PX2;
        sgb1 = wrapg(y0 + sy1 - 2) * NN + wrapg(x0 + sx1 - 2);
        suo1 = sy1 * PX2 + sx1;
    }

    // ---- fill coords: job0 = own center, job1 = halo ring (tid < 84) ----
    const int cfy = ty + 1, cfx = tx + 1;
    const int uoffc = (cfy + 1) * PX2 + (cfx + 1);
    const int hoc   = cfy * PX + cfx;
    const bool hasH = (tid < NHALO);
    int uoffh = 0, hoh = 0;
    {
        int hfy, hfx;
        if (tid < PX)            { hfy = 0;      hfx = tid; }
        else if (tid < 2 * PX)   { hfy = PY - 1; hfx = tid - PX; }
        else                     { const int r = tid - 2 * PX;
                                   hfy = 1 + (r >> 1); hfx = (r & 1) ? (PX - 1) : 0; }
        uoffh = (hfy + 1) * PX2 + (hfx + 1);
        hoh   = hfy * PX + hfx;
    }

    float pr0[4], pr1[4];
    float fzm[4], fzc[4], fzp[4];

    // ================= prologue =================
    stage_direct(u, T, sU, slot3(z0 - 2), z0 - 2, sgb0, suo0, sgb1, suo1, hasq1);
    stage_direct(u, T, sU, slot3(z0 - 1), z0 - 1, sgb0, suo0, sgb1, suo1, hasq1);
    stage_direct(u, T, sU, slot3(z0),     z0,     sgb0, suo0, sgb1, suo1, hasq1);
    __syncthreads();

    // prefetch plane z0+1 while filling flux z0-1
    prefetch_plane(u, T, z0 + 1, sgb0, sgb1, hasq1, pr0, pr1);
    flux_center(sU, sFh, slot3(z0 - 2), slot3(z0 - 1), slot3(z0), slot3(z0 - 1), uoffc, hoc, tx, fzm);
    if (hasH)
        flux_halo(sU, sFh, slot3(z0 - 2), slot3(z0 - 1), slot3(z0), slot3(z0 - 1), uoffh, hoh);
    __syncthreads();

    sts_prefetch(sU, slot3(z0 + 1), suo0, suo1, hasq1, pr0, pr1);
    __syncthreads();

    // prefetch plane z0+2 while filling flux z0
    prefetch_plane(u, T, z0 + 2, sgb0, sgb1, hasq1, pr0, pr1);
    flux_center(sU, sFh, slot3(z0 - 1), slot3(z0), slot3(z0 + 1), slot3(z0), uoffc, hoc, tx, fzc);
    if (hasH)
        flux_halo(sU, sFh, slot3(z0 - 1), slot3(z0), slot3(z0 + 1), slot3(z0), uoffh, hoh);
    __syncthreads();

    const int gx = x0 + tx, gy = y0 + ty;

    // ================= main loop =================
    for (int zi = 0; zi < CHUNK; zi++) {
        const int z = z0 + zi;

        // 1. commit prefetched plane z+2 (overwrites slot of z-1)
        sts_prefetch(sU, slot3(z + 2), suo0, suo1, hasq1, pr0, pr1);
        __syncthreads();

        // 2. prefetch plane z+3 for next iteration
        if (zi + 1 < CHUNK)
            prefetch_plane(u, T, z + 3, sgb0, sgb1, hasq1, pr0, pr1);

        // 3. fill flux plane z+1 from smem planes z, z+1, z+2
        flux_center(sU, sFh, slot3(z), slot3(z + 1), slot3(z + 2), slot3(z + 1), uoffc, hoc, tx, fzp);
        if (hasH)
            flux_halo(sU, sFh, slot3(z), slot3(z + 1), slot3(z + 2), slot3(z + 1), uoffh, hoh);
        __syncthreads();

        // 4. output plane z: y/x flux derivatives from smem, z from registers
        const float* HB = sFh + slot3(z) * SFH_PLANE;

        const float mom0 = (fzp[0] - fzm[0])                                       // t00 z
                         + (HB[0 * PY * PX + hoc + PX] - HB[0 * PY * PX + hoc - PX]) // t01 y
                         + (HB[1 * PY * PX + hoc + 1]  - HB[1 * PY * PX + hoc - 1]); // t02 x
        const float mom1 = (fzp[1] - fzm[1])                                       // t01 z
                         + (HB[2 * PY * PX + hoc + PX] - HB[2 * PY * PX + hoc - PX]) // t11 y
                         + (HB[3 * PY * PX + hoc + 1]  - HB[3 * PY * PX + hoc - 1]); // t12 x
        const float mom2 = (fzp[2] - fzm[2])                                       // t02 z
                         + (HB[3 * PY * PX + hoc + PX] - HB[3 * PY * PX + hoc - PX]) // t12 y
                         + (HB[4 * PY * PX + hoc + 1]  - HB[4 * PY * PX + hoc - 1]); // t22 x
        const float en   = (fzp[3] - fzm[3])                                       // E0 z
                         + (HB[5 * PY * PX + hoc + PX] - HB[5 * PY * PX + hoc - PX]) // E1 y
                         + (HB[6 * PY * PX + hoc + 1]  - HB[6 * PY * PX + hoc - 1]); // E2 x

        const int idx = z * NN2 + gy * NN + gx;
        out[0 * NN3 + idx] = 0.0f;
        out[1 * NN3 + idx] = mom0 * INV2DX;
        out[2 * NN3 + idx] = mom1 * INV2DX;
        out[3 * NN3 + idx] = mom2 * INV2DX;
        out[4 * NN3 + idx] = en * INV2DX;

        // rotate register flux pipeline
#pragma unroll
        for (int c = 0; c < 4; c++) { fzm[c] = fzc[c]; fzc[c] = fzp[c]; }
    }
}

extern "C" void kernel_launch(void* const* d_in, const int* in_sizes, int n_in,
                              void* d_out, int out_size)
{
    const float* u = (const float*)d_in[0];   // [3, N, N, N]
    const float* T = (const float*)d_in[1];   // [N, N, N]
    float* out = (float*)d_out;               // [5, N, N, N]

    cudaFuncSetAttribute(fused3, cudaFuncAttributeMaxDynamicSharedMemorySize, SMEM_BYTES);

    dim3 grid(NN / TX, NN / TY, NN / CHUNK);  // 6 x 24 x 4 = 576 blocks
    dim3 block(TX, TY, 1);
    fused3<<<grid, block, SMEM_BYTES>>>(u, T, out);
}